// round 3
// baseline (speedup 1.0000x reference)
#include <cuda_runtime.h>

#define BB 2
#define CC 256
#define NN 4096
#define RED 64
#define NH 4
#define HD 16
#define BH (BB*NH)
#define SCALE 0.25f
#define LOG2E 1.44269504f

// ---------------- scratch (device globals, no allocation) ----------------
__device__ float g_xn[(size_t)BB*NN*CC];     // 8 MB  normalized x, [b*N+n][c]
__device__ float g_q[(size_t)BH*NN*HD];      // 2 MB  [bh][n][d], pre-scaled
__device__ float g_k[(size_t)BH*NN*HD];
__device__ float g_v[(size_t)BH*NN*HD];
__device__ float g_dyn[(size_t)BB*NN];       // per-pixel scalar
__device__ float g_ctxT[(size_t)BB*RED*NN];  // 2 MB  [b][r][n]

__device__ __forceinline__ float ex2f(float x) {
    float r; asm("ex2.approx.ftz.f32 %0, %1;" : "=f"(r) : "f"(x)); return r;
}

// =====================================================================
// Kernel 1a: LayerNorm stats + dynamic-weight branch + write x_hat
// block = 32 pixels, 256 threads
// =====================================================================
__global__ void __launch_bounds__(256) ln_dyn_kernel(
    const float* __restrict__ x,
    const float* __restrict__ nw, const float* __restrict__ nb,
    const float* __restrict__ c1w, const float* __restrict__ c1b,
    const float* __restrict__ c2w, const float* __restrict__ c2b)
{
    __shared__ float xs[CC*33];
    __shared__ float mus[32], rss[32];
    __shared__ float dynp[8][32];

    const int tid  = threadIdx.x;
    const int tile = blockIdx.x;
    const int b    = tile >> 7;           // 128 tiles per batch
    const int n0   = (tile & 127) << 5;   // 32 pixels per tile

    const float* xb = x + (size_t)b*CC*NN;
    // load tile [256 channels][32 pixels], coalesced along n, stride-33 pad
    for (int idx = tid; idx < CC*32; idx += 256) {
        int c = idx >> 5, p = idx & 31;
        xs[c*33 + p] = xb[(size_t)c*NN + n0 + p];
    }
    __syncthreads();

    const int w = tid >> 5, lane = tid & 31;

    // LN stats: each warp handles 4 pixels, lane-parallel over channels
    for (int qi = 0; qi < 4; qi++) {
        int p = w*4 + qi;
        float s1 = 0.f, s2 = 0.f;
        #pragma unroll
        for (int k = 0; k < 8; k++) {
            float v = xs[(lane + 32*k)*33 + p];
            s1 += v; s2 = fmaf(v, v, s2);
        }
        #pragma unroll
        for (int off = 16; off > 0; off >>= 1) {
            s1 += __shfl_down_sync(0xffffffffu, s1, off);
            s2 += __shfl_down_sync(0xffffffffu, s2, off);
        }
        if (lane == 0) {
            float mu  = s1 * (1.f/256.f);
            float var = s2 * (1.f/256.f) - mu*mu;
            mus[p] = mu;
            rss[p] = rsqrtf(var + 1e-5f);
        }
    }
    __syncthreads();

    // dyn branch on RAW x: warp w owns conv1 outputs [w*16, w*16+16), lane = pixel
    {
        const int o0 = w*16;
        float acc[16];
        #pragma unroll
        for (int i = 0; i < 16; i++) acc[i] = c1b[o0+i];
        const float4* w14 = (const float4*)c1w;
        for (int c4 = 0; c4 < 64; c4++) {
            float x0 = xs[(c4*4+0)*33 + lane];
            float x1 = xs[(c4*4+1)*33 + lane];
            float x2 = xs[(c4*4+2)*33 + lane];
            float x3 = xs[(c4*4+3)*33 + lane];
            #pragma unroll
            for (int i = 0; i < 16; i++) {
                float4 wv = w14[(o0+i)*64 + c4];
                acc[i] = fmaf(wv.x, x0, acc[i]);
                acc[i] = fmaf(wv.y, x1, acc[i]);
                acc[i] = fmaf(wv.z, x2, acc[i]);
                acc[i] = fmaf(wv.w, x3, acc[i]);
            }
        }
        float part = 0.f;
        #pragma unroll
        for (int i = 0; i < 16; i++)
            part = fmaf(fmaxf(acc[i], 0.f), c2w[o0+i], part);
        dynp[w][lane] = part;
    }
    __syncthreads();
    if (tid < 32) {
        float d = c2b[0];
        #pragma unroll
        for (int g = 0; g < 8; g++) d += dynp[g][tid];
        g_dyn[b*NN + n0 + tid] = d;
    }

    // write x_hat pixel-major (coalesced along c)
    for (int idx = tid; idx < 32*CC; idx += 256) {
        int p = idx >> 8, c = idx & 255;
        float v = (xs[c*33 + p] - mus[p]) * rss[p] * nw[c] + nb[c];
        g_xn[((size_t)(b*NN + n0 + p))*CC + c] = v;
    }
}

// =====================================================================
// Kernel 1b: QKV projection. block = 16 pixels x 16 output-groups of 12.
// Q written pre-scaled by SCALE*log2(e) so attention can use raw EX2.
// =====================================================================
__global__ void __launch_bounds__(256) qkv_kernel(const float* __restrict__ qw)
{
    const int tid   = threadIdx.x;
    const int pixel = blockIdx.x*16 + (tid >> 4);
    const int o0    = (tid & 15) * 12;

    const float4* xn4 = ((const float4*)g_xn) + (size_t)pixel*64;
    const float4* qw4 = (const float4*)qw;

    float acc[12];
    #pragma unroll
    for (int i = 0; i < 12; i++) acc[i] = 0.f;

    for (int c4 = 0; c4 < 64; c4++) {
        float4 xv = xn4[c4];
        #pragma unroll
        for (int i = 0; i < 12; i++) {
            float4 wv = qw4[(o0+i)*64 + c4];
            acc[i] = fmaf(wv.x, xv.x, acc[i]);
            acc[i] = fmaf(wv.y, xv.y, acc[i]);
            acc[i] = fmaf(wv.z, xv.z, acc[i]);
            acc[i] = fmaf(wv.w, xv.w, acc[i]);
        }
    }

    const int b = pixel >> 12, n = pixel & 4095;
    #pragma unroll
    for (int i = 0; i < 12; i++) {
        int o = o0 + i;
        int part = o >> 6;
        int r = o & 63;
        int h = r >> 4, d = r & 15;
        size_t dst = ((size_t)(b*NH + h)*NN + n)*HD + d;
        float val = acc[i];
        if      (part == 0) g_q[dst] = val * (SCALE*LOG2E);
        else if (part == 1) g_k[dst] = val;
        else                g_v[dst] = val;
    }
}

// =====================================================================
// Kernel 2: flash attention. grid (32 qtiles, 8 bh), 128 threads.
// One query row per thread; K/V tiles (128x16) staged in smem.
// Online softmax in chunks of 8 columns. dyn scaling folded into epilogue.
// =====================================================================
__global__ void __launch_bounds__(128) attn_kernel()
{
    __shared__ float4 Ks[512];   // 128 rows x 4 float4
    __shared__ float4 Vs[512];

    const int tid = threadIdx.x;
    const int bh  = blockIdx.y;
    const int row = blockIdx.x*128 + tid;

    const float4* q4 = ((const float4*)g_q) + ((size_t)bh*NN + row)*4;
    const float4 q0 = q4[0], q1 = q4[1], q2 = q4[2], q3 = q4[3];

    float o[16];
    #pragma unroll
    for (int d = 0; d < 16; d++) o[d] = 0.f;
    float m = -1e30f, l = 0.f;

    const float4* kg = ((const float4*)g_k) + (size_t)bh*NN*4;
    const float4* vg = ((const float4*)g_v) + (size_t)bh*NN*4;

    for (int kt = 0; kt < 32; kt++) {
        __syncthreads();
        #pragma unroll
        for (int i = 0; i < 4; i++) {
            Ks[tid + i*128] = kg[kt*512 + tid + i*128];
            Vs[tid + i*128] = vg[kt*512 + tid + i*128];
        }
        __syncthreads();

        for (int ch = 0; ch < 16; ch++) {
            const int c0 = ch*8;
            float s[8];
            #pragma unroll
            for (int j = 0; j < 8; j++) {
                const float4* kk = &Ks[(c0+j)*4];
                float4 k0 = kk[0], k1 = kk[1], k2 = kk[2], k3 = kk[3];
                float sv =        q0.x*k0.x;
                sv = fmaf(q0.y, k0.y, sv); sv = fmaf(q0.z, k0.z, sv); sv = fmaf(q0.w, k0.w, sv);
                sv = fmaf(q1.x, k1.x, sv); sv = fmaf(q1.y, k1.y, sv); sv = fmaf(q1.z, k1.z, sv); sv = fmaf(q1.w, k1.w, sv);
                sv = fmaf(q2.x, k2.x, sv); sv = fmaf(q2.y, k2.y, sv); sv = fmaf(q2.z, k2.z, sv); sv = fmaf(q2.w, k2.w, sv);
                sv = fmaf(q3.x, k3.x, sv); sv = fmaf(q3.y, k3.y, sv); sv = fmaf(q3.z, k3.z, sv); sv = fmaf(q3.w, k3.w, sv);
                s[j] = sv;
            }
            float cm = s[0];
            #pragma unroll
            for (int j = 1; j < 8; j++) cm = fmaxf(cm, s[j]);
            float nm = fmaxf(m, cm);
            float sc = ex2f(m - nm);
            m = nm;
            l *= sc;
            #pragma unroll
            for (int d = 0; d < 16; d++) o[d] *= sc;
            #pragma unroll
            for (int j = 0; j < 8; j++) {
                float p = ex2f(s[j] - nm);
                l += p;
                const float4* vv = &Vs[(c0+j)*4];
                float4 v0 = vv[0], v1 = vv[1], v2 = vv[2], v3 = vv[3];
                o[0]  = fmaf(p, v0.x, o[0]);  o[1]  = fmaf(p, v0.y, o[1]);
                o[2]  = fmaf(p, v0.z, o[2]);  o[3]  = fmaf(p, v0.w, o[3]);
                o[4]  = fmaf(p, v1.x, o[4]);  o[5]  = fmaf(p, v1.y, o[5]);
                o[6]  = fmaf(p, v1.z, o[6]);  o[7]  = fmaf(p, v1.w, o[7]);
                o[8]  = fmaf(p, v2.x, o[8]);  o[9]  = fmaf(p, v2.y, o[9]);
                o[10] = fmaf(p, v2.z, o[10]); o[11] = fmaf(p, v2.w, o[11]);
                o[12] = fmaf(p, v3.x, o[12]); o[13] = fmaf(p, v3.y, o[13]);
                o[14] = fmaf(p, v3.z, o[14]); o[15] = fmaf(p, v3.w, o[15]);
            }
        }
    }

    const int b = bh >> 2, h = bh & 3;
    const float inv = g_dyn[b*NN + row] / l;   // softmax normalize * dyn row-scale
    #pragma unroll
    for (int d = 0; d < 16; d++)
        g_ctxT[((size_t)(b*RED + h*HD + d))*NN + row] = o[d] * inv;
}

// =====================================================================
// Kernel 3: out projection + residual + sigmoid. block = 32 pixels.
// =====================================================================
__global__ void __launch_bounds__(256) proj_kernel(
    const float* __restrict__ x,
    const float* __restrict__ ow,
    const float* __restrict__ gamma,
    float* __restrict__ out)
{
    __shared__ float cs[RED*33];
    const int tid  = threadIdx.x;
    const int tile = blockIdx.x;
    const int b    = tile >> 7;
    const int n0   = (tile & 127) << 5;

    for (int idx = tid; idx < RED*32; idx += 256) {
        int r = idx >> 5, p = idx & 31;
        cs[r*33 + p] = g_ctxT[((size_t)(b*RED + r))*NN + n0 + p];
    }
    __syncthreads();

    const int w = tid >> 5, lane = tid & 31;
    const float gm = gamma[0];

    for (int k = 0; k < 32; k++) {
        int c = w*32 + k;
        const float4* wr = (const float4*)(ow + c*RED);
        float acc = 0.f;
        #pragma unroll
        for (int r4 = 0; r4 < 16; r4++) {
            float4 wv = wr[r4];
            acc = fmaf(cs[(r4*4+0)*33 + lane], wv.x, acc);
            acc = fmaf(cs[(r4*4+1)*33 + lane], wv.y, acc);
            acc = fmaf(cs[(r4*4+2)*33 + lane], wv.z, acc);
            acc = fmaf(cs[(r4*4+3)*33 + lane], wv.w, acc);
        }
        size_t gi = ((size_t)b*CC + c)*NN + n0 + lane;
        float z = fmaf(gm, acc, x[gi]);
        float e = ex2f(-z * LOG2E);
        out[gi] = 1.f / (1.f + e);
    }
}

// =====================================================================
extern "C" void kernel_launch(void* const* d_in, const int* in_sizes, int n_in,
                              void* d_out, int out_size)
{
    const float* x     = (const float*)d_in[0];
    const float* nw    = (const float*)d_in[1];
    const float* nb    = (const float*)d_in[2];
    const float* qw    = (const float*)d_in[3];
    const float* ow    = (const float*)d_in[4];
    const float* c1w   = (const float*)d_in[5];
    const float* c1b   = (const float*)d_in[6];
    const float* c2w   = (const float*)d_in[7];
    const float* c2b   = (const float*)d_in[8];
    const float* gamma = (const float*)d_in[9];
    float* out = (float*)d_out;

    ln_dyn_kernel<<<256, 256>>>(x, nw, nb, c1w, c1b, c2w, c2b);
    qkv_kernel<<<512, 256>>>(qw);
    attn_kernel<<<dim3(32, 8), 128>>>();
    proj_kernel<<<256, 256>>>(x, ow, gamma, out);
}

// round 8
// speedup vs baseline: 1.1296x; 1.1296x over previous
#include <cuda_runtime.h>

#define BB 2
#define CC 256
#define NN 4096
#define RED 64
#define NH 4
#define HD 16
#define BH (BB*NH)
#define SPLIT 4
#define SCALE 0.25f
#define LOG2E 1.44269504f

// ---------------- scratch (device globals, no allocation) ----------------
__device__ float g_xn[(size_t)BB*NN*CC];         // normalized x, [b*N+n][c]
__device__ float g_q[(size_t)BH*NN*HD];          // [bh][n][d], pre-scaled by SCALE*log2e
__device__ float g_k[(size_t)BH*NN*HD];
__device__ float g_v[(size_t)BH*NN*HD];
__device__ float g_dyn[(size_t)BB*NN];           // per-pixel scalar
__device__ float g_ctxT[(size_t)BB*RED*NN];      // [b][r][n]
__device__ float g_po[SPLIT][(size_t)BH*NN*HD];  // partial ctx per split
__device__ float g_pl[SPLIT][(size_t)BH*NN];     // partial l per split
__device__ float g_kmax[BH];                     // max |k| row norm per bh

__device__ __forceinline__ float ex2f(float x) {
    float r; asm("ex2.approx.ftz.f32 %0, %1;" : "=f"(r) : "f"(x)); return r;
}
__device__ __forceinline__ unsigned long long pack2(float lo, float hi) {
    unsigned long long r; asm("mov.b64 %0, {%1, %2};" : "=l"(r) : "f"(lo), "f"(hi)); return r;
}
__device__ __forceinline__ float2 unpack2(unsigned long long v) {
    float2 r; asm("mov.b64 {%0, %1}, %2;" : "=f"(r.x), "=f"(r.y) : "l"(v)); return r;
}
#define FMA2(acc, a, b) asm("fma.rn.f32x2 %0, %1, %2, %0;" : "+l"(acc) : "l"(a), "l"(b))
__device__ __forceinline__ unsigned long long fma2i(
    unsigned long long a, unsigned long long b, unsigned long long c) {
    unsigned long long d; asm("fma.rn.f32x2 %0, %1, %2, %3;" : "=l"(d) : "l"(a), "l"(b), "l"(c));
    return d;
}

// =====================================================================
// Kernel 1a: LayerNorm stats + dynamic-weight branch + write x_hat
// =====================================================================
__global__ void __launch_bounds__(256) ln_dyn_kernel(
    const float* __restrict__ x,
    const float* __restrict__ nw, const float* __restrict__ nb,
    const float* __restrict__ c1w, const float* __restrict__ c1b,
    const float* __restrict__ c2w, const float* __restrict__ c2b)
{
    __shared__ float xs[CC*33];
    __shared__ float mus[32], rss[32];
    __shared__ float dynp[8][32];

    const int tid  = threadIdx.x;
    const int tile = blockIdx.x;
    const int b    = tile >> 7;
    const int n0   = (tile & 127) << 5;

    const float* xb = x + (size_t)b*CC*NN;
    for (int idx = tid; idx < CC*32; idx += 256) {
        int c = idx >> 5, p = idx & 31;
        xs[c*33 + p] = xb[(size_t)c*NN + n0 + p];
    }
    __syncthreads();

    const int w = tid >> 5, lane = tid & 31;

    for (int qi = 0; qi < 4; qi++) {
        int p = w*4 + qi;
        float s1 = 0.f, s2 = 0.f;
        #pragma unroll
        for (int k = 0; k < 8; k++) {
            float v = xs[(lane + 32*k)*33 + p];
            s1 += v; s2 = fmaf(v, v, s2);
        }
        #pragma unroll
        for (int off = 16; off > 0; off >>= 1) {
            s1 += __shfl_down_sync(0xffffffffu, s1, off);
            s2 += __shfl_down_sync(0xffffffffu, s2, off);
        }
        if (lane == 0) {
            float mu  = s1 * (1.f/256.f);
            float var = s2 * (1.f/256.f) - mu*mu;
            mus[p] = mu;
            rss[p] = rsqrtf(var + 1e-5f);
        }
    }
    __syncthreads();

    {
        const int o0 = w*16;
        float acc[16];
        #pragma unroll
        for (int i = 0; i < 16; i++) acc[i] = c1b[o0+i];
        const float4* w14 = (const float4*)c1w;
        for (int c4 = 0; c4 < 64; c4++) {
            float x0 = xs[(c4*4+0)*33 + lane];
            float x1 = xs[(c4*4+1)*33 + lane];
            float x2 = xs[(c4*4+2)*33 + lane];
            float x3 = xs[(c4*4+3)*33 + lane];
            #pragma unroll
            for (int i = 0; i < 16; i++) {
                float4 wv = w14[(o0+i)*64 + c4];
                acc[i] = fmaf(wv.x, x0, acc[i]);
                acc[i] = fmaf(wv.y, x1, acc[i]);
                acc[i] = fmaf(wv.z, x2, acc[i]);
                acc[i] = fmaf(wv.w, x3, acc[i]);
            }
        }
        float part = 0.f;
        #pragma unroll
        for (int i = 0; i < 16; i++)
            part = fmaf(fmaxf(acc[i], 0.f), c2w[o0+i], part);
        dynp[w][lane] = part;
    }
    __syncthreads();
    if (tid < 32) {
        float d = c2b[0];
        #pragma unroll
        for (int g = 0; g < 8; g++) d += dynp[g][tid];
        g_dyn[b*NN + n0 + tid] = d;
    }

    for (int idx = tid; idx < 32*CC; idx += 256) {
        int p = idx >> 8, c = idx & 255;
        float v = (xs[c*33 + p] - mus[p]) * rss[p] * nw[c] + nb[c];
        g_xn[((size_t)(b*NN + n0 + p))*CC + c] = v;
    }
}

// =====================================================================
// Kernel 1b: QKV projection (Q pre-scaled by SCALE*log2e)
// =====================================================================
__global__ void __launch_bounds__(256) qkv_kernel(const float* __restrict__ qw)
{
    const int tid   = threadIdx.x;
    const int pixel = blockIdx.x*16 + (tid >> 4);
    const int o0    = (tid & 15) * 12;

    const float4* xn4 = ((const float4*)g_xn) + (size_t)pixel*64;
    const float4* qw4 = (const float4*)qw;

    float acc[12];
    #pragma unroll
    for (int i = 0; i < 12; i++) acc[i] = 0.f;

    for (int c4 = 0; c4 < 64; c4++) {
        float4 xv = xn4[c4];
        #pragma unroll
        for (int i = 0; i < 12; i++) {
            float4 wv = qw4[(o0+i)*64 + c4];
            acc[i] = fmaf(wv.x, xv.x, acc[i]);
            acc[i] = fmaf(wv.y, xv.y, acc[i]);
            acc[i] = fmaf(wv.z, xv.z, acc[i]);
            acc[i] = fmaf(wv.w, xv.w, acc[i]);
        }
    }

    const int b = pixel >> 12, n = pixel & 4095;
    #pragma unroll
    for (int i = 0; i < 12; i++) {
        int o = o0 + i;
        int part = o >> 6;
        int r = o & 63;
        int h = r >> 4, d = r & 15;
        size_t dst = ((size_t)(b*NH + h)*NN + n)*HD + d;
        float val = acc[i];
        if      (part == 0) g_q[dst] = val * (SCALE*LOG2E);
        else if (part == 1) g_k[dst] = val;
        else                g_v[dst] = val;
    }
}

// =====================================================================
// Kernel 1c: per-bh max row-norm of K  (for the fixed softmax offset)
// =====================================================================
__global__ void __launch_bounds__(256) kmax_kernel()
{
    __shared__ float red[256];
    const int bh = blockIdx.x, tid = threadIdx.x;
    const float4* kg = ((const float4*)g_k) + (size_t)bh*NN*4;
    float mx = 0.f;
    for (int r = tid; r < NN; r += 256) {
        float4 a = kg[r*4+0], b = kg[r*4+1], c = kg[r*4+2], d = kg[r*4+3];
        float s = a.x*a.x;
        s = fmaf(a.y,a.y,s); s = fmaf(a.z,a.z,s); s = fmaf(a.w,a.w,s);
        s = fmaf(b.x,b.x,s); s = fmaf(b.y,b.y,s); s = fmaf(b.z,b.z,s); s = fmaf(b.w,b.w,s);
        s = fmaf(c.x,c.x,s); s = fmaf(c.y,c.y,s); s = fmaf(c.z,c.z,s); s = fmaf(c.w,c.w,s);
        s = fmaf(d.x,d.x,s); s = fmaf(d.y,d.y,s); s = fmaf(d.z,d.z,s); s = fmaf(d.w,d.w,s);
        mx = fmaxf(mx, s);
    }
    red[tid] = mx; __syncthreads();
    for (int off = 128; off > 0; off >>= 1) {
        if (tid < off) red[tid] = fmaxf(red[tid], red[tid+off]);
        __syncthreads();
    }
    if (tid == 0) g_kmax[bh] = sqrtf(red[0]);
}

// =====================================================================
// Kernel 2: flash attention, f32x2 packed, fixed per-row softmax offset,
// split-KV x4. grid (32 qtiles, 8 bh, 4 splits), 128 threads.
// =====================================================================
__global__ void __launch_bounds__(128) attn_kernel()
{
    __shared__ ulonglong2 Ks[512];   // 128 rows x 4 x 16B
    __shared__ ulonglong2 Vs[512];

    const int tid = threadIdx.x;
    const int bh  = blockIdx.y;
    const int z   = blockIdx.z;
    const int row = blockIdx.x*128 + tid;

    // prologue: load q (scaled space), |q|, pack into f32x2 pairs
    const float4* qf = ((const float4*)g_q) + ((size_t)bh*NN + row)*4;
    const float4 qa = qf[0], qb = qf[1], qc = qf[2], qd = qf[3];
    float qq = qa.x*qa.x;
    qq = fmaf(qa.y,qa.y,qq); qq = fmaf(qa.z,qa.z,qq); qq = fmaf(qa.w,qa.w,qq);
    qq = fmaf(qb.x,qb.x,qq); qq = fmaf(qb.y,qb.y,qq); qq = fmaf(qb.z,qb.z,qq); qq = fmaf(qb.w,qb.w,qq);
    qq = fmaf(qc.x,qc.x,qq); qq = fmaf(qc.y,qc.y,qq); qq = fmaf(qc.z,qc.z,qq); qq = fmaf(qc.w,qc.w,qq);
    qq = fmaf(qd.x,qd.x,qq); qq = fmaf(qd.y,qd.y,qq); qq = fmaf(qd.z,qd.z,qq); qq = fmaf(qd.w,qd.w,qq);
    const float m = sqrtf(qq) * g_kmax[bh];   // >= any score (log2 space)

    const unsigned long long q01 = pack2(qa.x, qa.y), q23 = pack2(qa.z, qa.w);
    const unsigned long long q45 = pack2(qb.x, qb.y), q67 = pack2(qb.z, qb.w);
    const unsigned long long q89 = pack2(qc.x, qc.y), qab = pack2(qc.z, qc.w);
    const unsigned long long qcd = pack2(qd.x, qd.y), qef = pack2(qd.z, qd.w);
    const unsigned long long minit = pack2(-m, 0.f);
    const unsigned long long zero2 = pack2(0.f, 0.f);

    unsigned long long o[8];
    #pragma unroll
    for (int d = 0; d < 8; d++) o[d] = zero2;
    float l0 = 0.f, l1 = 0.f;

    const ulonglong2* kg = ((const ulonglong2*)g_k) + (size_t)bh*NN*4;
    const ulonglong2* vg = ((const ulonglong2*)g_v) + (size_t)bh*NN*4;

    for (int kt = z*8; kt < z*8 + 8; kt++) {
        __syncthreads();
        #pragma unroll
        for (int i = 0; i < 4; i++) {
            Ks[tid + i*128] = kg[kt*512 + tid + i*128];
            Vs[tid + i*128] = vg[kt*512 + tid + i*128];
        }
        __syncthreads();

        #pragma unroll 1
        for (int c0 = 0; c0 < 128; c0 += 8) {
            unsigned long long sacc[8];
            #pragma unroll
            for (int j = 0; j < 8; j++) {
                const ulonglong2* kk = &Ks[(c0+j)*4];
                const ulonglong2 k0 = kk[0], k1 = kk[1], k2 = kk[2], k3 = kk[3];
                unsigned long long a = fma2i(q01, k0.x, minit);
                FMA2(a, q23, k0.y); FMA2(a, q45, k1.x); FMA2(a, q67, k1.y);
                FMA2(a, q89, k2.x); FMA2(a, qab, k2.y); FMA2(a, qcd, k3.x); FMA2(a, qef, k3.y);
                sacc[j] = a;
            }
            float p[8];
            #pragma unroll
            for (int j = 0; j < 8; j++) {
                float2 s = unpack2(sacc[j]);
                p[j] = ex2f(s.x + s.y);     // s - m <= ~0, never overflows
            }
            #pragma unroll
            for (int j = 0; j < 8; j++) {
                if (j & 1) l1 += p[j]; else l0 += p[j];
                const unsigned long long pp = pack2(p[j], p[j]);
                const ulonglong2* vv = &Vs[(c0+j)*4];
                const ulonglong2 v0 = vv[0], v1 = vv[1], v2 = vv[2], v3 = vv[3];
                FMA2(o[0], pp, v0.x); FMA2(o[1], pp, v0.y);
                FMA2(o[2], pp, v1.x); FMA2(o[3], pp, v1.y);
                FMA2(o[4], pp, v2.x); FMA2(o[5], pp, v2.y);
                FMA2(o[6], pp, v3.x); FMA2(o[7], pp, v3.y);
            }
        }
    }

    float* po = g_po[z] + ((size_t)bh*NN + row)*16;
    #pragma unroll
    for (int i = 0; i < 4; i++) {
        ulonglong2 w; w.x = o[2*i]; w.y = o[2*i+1];
        *(ulonglong2*)(po + i*4) = w;
    }
    g_pl[z][(size_t)bh*NN + row] = l0 + l1;
}

// =====================================================================
// Kernel 2b: combine split partials, normalize, apply dyn, write ctxT
// =====================================================================
__global__ void __launch_bounds__(256) combine_kernel()
{
    const int idx = blockIdx.x*256 + threadIdx.x;   // bh*NN + row
    const int bh = idx >> 12, row = idx & 4095;
    const int b = bh >> 2, h = bh & 3;

    float l = 0.f;
    float acc[16];
    #pragma unroll
    for (int d = 0; d < 16; d++) acc[d] = 0.f;

    #pragma unroll
    for (int z = 0; z < SPLIT; z++) {
        l += g_pl[z][idx];
        const float4* po = (const float4*)(g_po[z] + (size_t)idx*16);
        #pragma unroll
        for (int i = 0; i < 4; i++) {
            float4 v = po[i];
            acc[i*4+0] += v.x; acc[i*4+1] += v.y;
            acc[i*4+2] += v.z; acc[i*4+3] += v.w;
        }
    }
    const float inv = g_dyn[b*NN + row] / l;
    #pragma unroll
    for (int d = 0; d < 16; d++)
        g_ctxT[((size_t)(b*RED + h*HD + d))*NN + row] = acc[d] * inv;
}

// =====================================================================
// Kernel 3: out projection + residual + sigmoid
// =====================================================================
__global__ void __launch_bounds__(256) proj_kernel(
    const float* __restrict__ x,
    const float* __restrict__ ow,
    const float* __restrict__ gamma,
    float* __restrict__ out)
{
    __shared__ float cs[RED*33];
    const int tid  = threadIdx.x;
    const int tile = blockIdx.x;
    const int b    = tile >> 7;
    const int n0   = (tile & 127) << 5;

    for (int idx = tid; idx < RED*32; idx += 256) {
        int r = idx >> 5, p = idx & 31;
        cs[r*33 + p] = g_ctxT[((size_t)(b*RED + r))*NN + n0 + p];
    }
    __syncthreads();

    const int w = tid >> 5, lane = tid & 31;
    const float gm = gamma[0];

    for (int k = 0; k < 32; k++) {
        int c = w*32 + k;
        const float4* wr = (const float4*)(ow + c*RED);
        float acc = 0.f;
        #pragma unroll
        for (int r4 = 0; r4 < 16; r4++) {
            float4 wv = wr[r4];
            acc = fmaf(cs[(r4*4+0)*33 + lane], wv.x, acc);
            acc = fmaf(cs[(r4*4+1)*33 + lane], wv.y, acc);
            acc = fmaf(cs[(r4*4+2)*33 + lane], wv.z, acc);
            acc = fmaf(cs[(r4*4+3)*33 + lane], wv.w, acc);
        }
        size_t gi = ((size_t)b*CC + c)*NN + n0 + lane;
        float z = fmaf(gm, acc, x[gi]);
        float e = ex2f(-z * LOG2E);
        out[gi] = 1.f / (1.f + e);
    }
}

// =====================================================================
extern "C" void kernel_launch(void* const* d_in, const int* in_sizes, int n_in,
                              void* d_out, int out_size)
{
    const float* x     = (const float*)d_in[0];
    const float* nw    = (const float*)d_in[1];
    const float* nb    = (const float*)d_in[2];
    const float* qw    = (const float*)d_in[3];
    const float* ow    = (const float*)d_in[4];
    const float* c1w   = (const float*)d_in[5];
    const float* c1b   = (const float*)d_in[6];
    const float* c2w   = (const float*)d_in[7];
    const float* c2b   = (const float*)d_in[8];
    const float* gamma = (const float*)d_in[9];
    float* out = (float*)d_out;

    ln_dyn_kernel<<<256, 256>>>(x, nw, nb, c1w, c1b, c2w, c2b);
    qkv_kernel<<<512, 256>>>(qw);
    kmax_kernel<<<8, 256>>>();
    attn_kernel<<<dim3(32, 8, SPLIT), 128>>>();
    combine_kernel<<<128, 256>>>();
    proj_kernel<<<256, 256>>>(x, ow, gamma, out);
}

// round 9
// speedup vs baseline: 2.2688x; 2.0085x over previous
#include <cuda_runtime.h>

#define BB 2
#define CC 256
#define NN 4096
#define RED 64
#define NH 4
#define HD 16
#define BH (BB*NH)
#define SPLIT 4
#define SCALE 0.25f
#define LOG2E 1.44269504f

// ---------------- scratch (device globals, no allocation) ----------------
__device__ float g_xn[(size_t)BB*NN*CC];         // normalized x, [b*N+n][c]
__device__ float g_q[(size_t)BH*NN*HD];          // [bh][n][d], pre-scaled by SCALE*log2e
__device__ float g_k[(size_t)BH*NN*HD];
__device__ float g_v[(size_t)BH*NN*HD];
__device__ float g_dyn[(size_t)BB*NN];           // per-pixel scalar
__device__ float g_ctxT[(size_t)BB*RED*NN];      // [b][r][n]
__device__ float g_po[SPLIT][(size_t)BH*NN*HD];  // partial ctx per split
__device__ float g_pl[SPLIT][(size_t)BH*NN];     // partial l per split
__device__ float g_kmax[BH];                     // max |k| row norm per bh

__device__ __forceinline__ float ex2f(float x) {
    float r; asm("ex2.approx.ftz.f32 %0, %1;" : "=f"(r) : "f"(x)); return r;
}
__device__ __forceinline__ unsigned long long pack2(float lo, float hi) {
    unsigned long long r; asm("mov.b64 %0, {%1, %2};" : "=l"(r) : "f"(lo), "f"(hi)); return r;
}
__device__ __forceinline__ float2 unpack2(unsigned long long v) {
    float2 r; asm("mov.b64 {%0, %1}, %2;" : "=f"(r.x), "=f"(r.y) : "l"(v)); return r;
}
#define FMA2(acc, a, b) asm("fma.rn.f32x2 %0, %1, %2, %0;" : "+l"(acc) : "l"(a), "l"(b))
__device__ __forceinline__ unsigned long long fma2i(
    unsigned long long a, unsigned long long b, unsigned long long c) {
    unsigned long long d; asm("fma.rn.f32x2 %0, %1, %2, %3;" : "=l"(d) : "l"(a), "l"(b), "l"(c));
    return d;
}
__device__ __forceinline__ unsigned long long mul2i(
    unsigned long long a, unsigned long long b) {
    unsigned long long d; asm("mul.rn.f32x2 %0, %1, %2;" : "=l"(d) : "l"(a), "l"(b));
    return d;
}

// =====================================================================
// Kernel 1a: LayerNorm stats + dynamic-weight branch + write x_hat
// =====================================================================
__global__ void __launch_bounds__(256) ln_dyn_kernel(
    const float* __restrict__ x,
    const float* __restrict__ nw, const float* __restrict__ nb,
    const float* __restrict__ c1w, const float* __restrict__ c1b,
    const float* __restrict__ c2w, const float* __restrict__ c2b)
{
    __shared__ float xs[CC*33];
    __shared__ float mus[32], rss[32];
    __shared__ float dynp[8][32];

    const int tid  = threadIdx.x;
    const int tile = blockIdx.x;
    const int b    = tile >> 7;
    const int n0   = (tile & 127) << 5;

    const float* xb = x + (size_t)b*CC*NN;
    for (int idx = tid; idx < CC*32; idx += 256) {
        int c = idx >> 5, p = idx & 31;
        xs[c*33 + p] = xb[(size_t)c*NN + n0 + p];
    }
    __syncthreads();

    const int w = tid >> 5, lane = tid & 31;

    for (int qi = 0; qi < 4; qi++) {
        int p = w*4 + qi;
        float s1 = 0.f, s2 = 0.f;
        #pragma unroll
        for (int k = 0; k < 8; k++) {
            float v = xs[(lane + 32*k)*33 + p];
            s1 += v; s2 = fmaf(v, v, s2);
        }
        #pragma unroll
        for (int off = 16; off > 0; off >>= 1) {
            s1 += __shfl_down_sync(0xffffffffu, s1, off);
            s2 += __shfl_down_sync(0xffffffffu, s2, off);
        }
        if (lane == 0) {
            float mu  = s1 * (1.f/256.f);
            float var = s2 * (1.f/256.f) - mu*mu;
            mus[p] = mu;
            rss[p] = rsqrtf(var + 1e-5f);
        }
    }
    __syncthreads();

    {
        const int o0 = w*16;
        float acc[16];
        #pragma unroll
        for (int i = 0; i < 16; i++) acc[i] = c1b[o0+i];
        const float4* w14 = (const float4*)c1w;
        for (int c4 = 0; c4 < 64; c4++) {
            float x0 = xs[(c4*4+0)*33 + lane];
            float x1 = xs[(c4*4+1)*33 + lane];
            float x2 = xs[(c4*4+2)*33 + lane];
            float x3 = xs[(c4*4+3)*33 + lane];
            #pragma unroll
            for (int i = 0; i < 16; i++) {
                float4 wv = w14[(o0+i)*64 + c4];
                acc[i] = fmaf(wv.x, x0, acc[i]);
                acc[i] = fmaf(wv.y, x1, acc[i]);
                acc[i] = fmaf(wv.z, x2, acc[i]);
                acc[i] = fmaf(wv.w, x3, acc[i]);
            }
        }
        float part = 0.f;
        #pragma unroll
        for (int i = 0; i < 16; i++)
            part = fmaf(fmaxf(acc[i], 0.f), c2w[o0+i], part);
        dynp[w][lane] = part;
    }
    __syncthreads();
    if (tid < 32) {
        float d = c2b[0];
        #pragma unroll
        for (int g = 0; g < 8; g++) d += dynp[g][tid];
        g_dyn[b*NN + n0 + tid] = d;
    }

    for (int idx = tid; idx < 32*CC; idx += 256) {
        int p = idx >> 8, c = idx & 255;
        float v = (xs[c*33 + p] - mus[p]) * rss[p] * nw[c] + nb[c];
        g_xn[((size_t)(b*NN + n0 + p))*CC + c] = v;
    }
}

// =====================================================================
// Kernel 1b: QKV projection as smem-tiled GEMM.
// [8192 px x 256] x [256 x 192].  BM=64 px, BN=192 (all), BK=32.
// Accumulators pack (o, o+1) output pairs -> f32x2 FMA, 8B stores.
// grid 128 blocks x 256 threads. Q pre-scaled by SCALE*log2e.
// =====================================================================
__global__ void __launch_bounds__(256) qkv_kernel(const float* __restrict__ qw)
{
    __shared__ float xs[64*33];      // [pixel][k], pad 33
    __shared__ float ws[32*194];     // [k][out], pad 194 (8B-aligned rows)

    const int tid = threadIdx.x;
    const int px0 = blockIdx.x*64;
    const int opg = tid & 15;        // out-pair group: outputs o0..o0+11 (6 pairs)
    const int pxg = tid >> 4;        // pixel group: 4 pixels
    const int o0  = opg*12;
    const int p0  = pxg*4;

    unsigned long long acc[6][4];
    #pragma unroll
    for (int i = 0; i < 6; i++)
        #pragma unroll
        for (int j = 0; j < 4; j++) acc[i][j] = 0ull;

    for (int it = 0; it < 8; it++) {
        const int k0 = it*32;
        __syncthreads();
        // stage x tile: 64 px x 32 k (coalesced read, stride-1 write)
        for (int i = tid; i < 64*32; i += 256) {
            int p = i >> 5, c = i & 31;
            xs[p*33 + c] = g_xn[(size_t)(px0+p)*256 + k0 + c];
        }
        // stage w tile transposed: [k][out] (coalesced read, 2-way write)
        for (int i = tid; i < 192*32; i += 256) {
            int o = i >> 5, c = i & 31;
            ws[c*194 + o] = qw[(size_t)o*256 + k0 + c];
        }
        __syncthreads();

        #pragma unroll 4
        for (int kk = 0; kk < 32; kk++) {
            unsigned long long xv[4];
            #pragma unroll
            for (int j = 0; j < 4; j++) {
                float v = xs[(p0+j)*33 + kk];
                xv[j] = pack2(v, v);
            }
            #pragma unroll
            for (int i = 0; i < 6; i++) {
                unsigned long long wv =
                    *(const unsigned long long*)&ws[kk*194 + o0 + 2*i];
                FMA2(acc[i][0], wv, xv[0]);
                FMA2(acc[i][1], wv, xv[1]);
                FMA2(acc[i][2], wv, xv[2]);
                FMA2(acc[i][3], wv, xv[3]);
            }
        }
    }

    const unsigned long long qs2 = pack2(SCALE*LOG2E, SCALE*LOG2E);
    #pragma unroll
    for (int i = 0; i < 6; i++) {
        const int o = o0 + 2*i;
        const int part = o >> 6;
        const int r = o & 63;
        const int h = r >> 4, d = r & 15;   // d even, pair (d, d+1)
        #pragma unroll
        for (int j = 0; j < 4; j++) {
            const int px = px0 + p0 + j;
            const int b = px >> 12, n = px & 4095;
            size_t dst = ((size_t)(b*NH + h)*NN + n)*HD + d;
            unsigned long long val = acc[i][j];
            if      (part == 0) *(unsigned long long*)(g_q + dst) = mul2i(val, qs2);
            else if (part == 1) *(unsigned long long*)(g_k + dst) = val;
            else                *(unsigned long long*)(g_v + dst) = val;
        }
    }
}

// =====================================================================
// Kernel 1c: per-bh max row-norm of K
// =====================================================================
__global__ void __launch_bounds__(256) kmax_kernel()
{
    __shared__ float red[256];
    const int bh = blockIdx.x, tid = threadIdx.x;
    const float4* kg = ((const float4*)g_k) + (size_t)bh*NN*4;
    float mx = 0.f;
    for (int r = tid; r < NN; r += 256) {
        float4 a = kg[r*4+0], b = kg[r*4+1], c = kg[r*4+2], d = kg[r*4+3];
        float s = a.x*a.x;
        s = fmaf(a.y,a.y,s); s = fmaf(a.z,a.z,s); s = fmaf(a.w,a.w,s);
        s = fmaf(b.x,b.x,s); s = fmaf(b.y,b.y,s); s = fmaf(b.z,b.z,s); s = fmaf(b.w,b.w,s);
        s = fmaf(c.x,c.x,s); s = fmaf(c.y,c.y,s); s = fmaf(c.z,c.z,s); s = fmaf(c.w,c.w,s);
        s = fmaf(d.x,d.x,s); s = fmaf(d.y,d.y,s); s = fmaf(d.z,d.z,s); s = fmaf(d.w,d.w,s);
        mx = fmaxf(mx, s);
    }
    red[tid] = mx; __syncthreads();
    for (int off = 128; off > 0; off >>= 1) {
        if (tid < off) red[tid] = fmaxf(red[tid], red[tid+off]);
        __syncthreads();
    }
    if (tid == 0) g_kmax[bh] = sqrtf(red[0]);
}

// =====================================================================
// Kernel 2: flash attention, f32x2 packed, fixed per-row softmax offset,
// split-KV x4, TWO query rows per thread (K/V smem reads amortized 2x).
// grid (16 qtiles, 8 bh, 4 splits), 128 threads.
// =====================================================================
__global__ void __launch_bounds__(128) attn_kernel()
{
    __shared__ ulonglong2 Ks[512];   // 128 rows x 4 x 16B
    __shared__ ulonglong2 Vs[512];

    const int tid = threadIdx.x;
    const int bh  = blockIdx.y;
    const int z   = blockIdx.z;
    const int rowA = blockIdx.x*256 + tid;     // rowB = rowA + 128
    const float km = g_kmax[bh];

    // ---- load q for both rows, compute fixed offsets, pack ----
    const float4* qfA = ((const float4*)g_q) + ((size_t)bh*NN + rowA)*4;
    const float4 a0 = qfA[0], a1 = qfA[1], a2 = qfA[2], a3 = qfA[3];
    const float4 b0 = qfA[512], b1 = qfA[513], b2 = qfA[514], b3 = qfA[515];

    float nA = a0.x*a0.x;
    nA = fmaf(a0.y,a0.y,nA); nA = fmaf(a0.z,a0.z,nA); nA = fmaf(a0.w,a0.w,nA);
    nA = fmaf(a1.x,a1.x,nA); nA = fmaf(a1.y,a1.y,nA); nA = fmaf(a1.z,a1.z,nA); nA = fmaf(a1.w,a1.w,nA);
    nA = fmaf(a2.x,a2.x,nA); nA = fmaf(a2.y,a2.y,nA); nA = fmaf(a2.z,a2.z,nA); nA = fmaf(a2.w,a2.w,nA);
    nA = fmaf(a3.x,a3.x,nA); nA = fmaf(a3.y,a3.y,nA); nA = fmaf(a3.z,a3.z,nA); nA = fmaf(a3.w,a3.w,nA);
    float nB = b0.x*b0.x;
    nB = fmaf(b0.y,b0.y,nB); nB = fmaf(b0.z,b0.z,nB); nB = fmaf(b0.w,b0.w,nB);
    nB = fmaf(b1.x,b1.x,nB); nB = fmaf(b1.y,b1.y,nB); nB = fmaf(b1.z,b1.z,nB); nB = fmaf(b1.w,b1.w,nB);
    nB = fmaf(b2.x,b2.x,nB); nB = fmaf(b2.y,b2.y,nB); nB = fmaf(b2.z,b2.z,nB); nB = fmaf(b2.w,b2.w,nB);
    nB = fmaf(b3.x,b3.x,nB); nB = fmaf(b3.y,b3.y,nB); nB = fmaf(b3.z,b3.z,nB); nB = fmaf(b3.w,b3.w,nB);
    const unsigned long long miA = pack2(-sqrtf(nA)*km, 0.f);
    const unsigned long long miB = pack2(-sqrtf(nB)*km, 0.f);

    const unsigned long long qA[8] = {
        pack2(a0.x,a0.y), pack2(a0.z,a0.w), pack2(a1.x,a1.y), pack2(a1.z,a1.w),
        pack2(a2.x,a2.y), pack2(a2.z,a2.w), pack2(a3.x,a3.y), pack2(a3.z,a3.w)};
    const unsigned long long qB[8] = {
        pack2(b0.x,b0.y), pack2(b0.z,b0.w), pack2(b1.x,b1.y), pack2(b1.z,b1.w),
        pack2(b2.x,b2.y), pack2(b2.z,b2.w), pack2(b3.x,b3.y), pack2(b3.z,b3.w)};

    const unsigned long long zero2 = pack2(0.f, 0.f);
    unsigned long long oA[8], oB[8];
    #pragma unroll
    for (int d = 0; d < 8; d++) { oA[d] = zero2; oB[d] = zero2; }
    float lA = 0.f, lB = 0.f;

    const ulonglong2* kg = ((const ulonglong2*)g_k) + (size_t)bh*NN*4;
    const ulonglong2* vg = ((const ulonglong2*)g_v) + (size_t)bh*NN*4;

    for (int kt = z*8; kt < z*8 + 8; kt++) {
        __syncthreads();
        #pragma unroll
        for (int i = 0; i < 4; i++) {
            Ks[tid + i*128] = kg[kt*512 + tid + i*128];
            Vs[tid + i*128] = vg[kt*512 + tid + i*128];
        }
        __syncthreads();

        #pragma unroll 1
        for (int c0 = 0; c0 < 128; c0 += 4) {
            float pA[4], pB[4];
            #pragma unroll
            for (int j = 0; j < 4; j++) {
                const ulonglong2* kk = &Ks[(c0+j)*4];
                const ulonglong2 k0 = kk[0], k1 = kk[1], k2 = kk[2], k3 = kk[3];
                unsigned long long sa = fma2i(qA[0], k0.x, miA);
                unsigned long long sb = fma2i(qB[0], k0.x, miB);
                FMA2(sa, qA[1], k0.y); FMA2(sb, qB[1], k0.y);
                FMA2(sa, qA[2], k1.x); FMA2(sb, qB[2], k1.x);
                FMA2(sa, qA[3], k1.y); FMA2(sb, qB[3], k1.y);
                FMA2(sa, qA[4], k2.x); FMA2(sb, qB[4], k2.x);
                FMA2(sa, qA[5], k2.y); FMA2(sb, qB[5], k2.y);
                FMA2(sa, qA[6], k3.x); FMA2(sb, qB[6], k3.x);
                FMA2(sa, qA[7], k3.y); FMA2(sb, qB[7], k3.y);
                float2 va = unpack2(sa), vb = unpack2(sb);
                pA[j] = ex2f(va.x + va.y);
                pB[j] = ex2f(vb.x + vb.y);
            }
            #pragma unroll
            for (int j = 0; j < 4; j++) {
                lA += pA[j]; lB += pB[j];
                const unsigned long long ppA = pack2(pA[j], pA[j]);
                const unsigned long long ppB = pack2(pB[j], pB[j]);
                const ulonglong2* vv = &Vs[(c0+j)*4];
                const ulonglong2 v0 = vv[0], v1 = vv[1], v2 = vv[2], v3 = vv[3];
                FMA2(oA[0], ppA, v0.x); FMA2(oB[0], ppB, v0.x);
                FMA2(oA[1], ppA, v0.y); FMA2(oB[1], ppB, v0.y);
                FMA2(oA[2], ppA, v1.x); FMA2(oB[2], ppB, v1.x);
                FMA2(oA[3], ppA, v1.y); FMA2(oB[3], ppB, v1.y);
                FMA2(oA[4], ppA, v2.x); FMA2(oB[4], ppB, v2.x);
                FMA2(oA[5], ppA, v2.y); FMA2(oB[5], ppB, v2.y);
                FMA2(oA[6], ppA, v3.x); FMA2(oB[6], ppB, v3.x);
                FMA2(oA[7], ppA, v3.y); FMA2(oB[7], ppB, v3.y);
            }
        }
    }

    float* poA = g_po[z] + ((size_t)bh*NN + rowA)*16;
    #pragma unroll
    for (int i = 0; i < 4; i++) {
        ulonglong2 w; w.x = oA[2*i]; w.y = oA[2*i+1];
        *(ulonglong2*)(poA + i*4) = w;
    }
    float* poB = poA + 128*16;
    #pragma unroll
    for (int i = 0; i < 4; i++) {
        ulonglong2 w; w.x = oB[2*i]; w.y = oB[2*i+1];
        *(ulonglong2*)(poB + i*4) = w;
    }
    g_pl[z][(size_t)bh*NN + rowA]       = lA;
    g_pl[z][(size_t)bh*NN + rowA + 128] = lB;
}

// =====================================================================
// Kernel 2b: combine split partials, normalize, apply dyn, write ctxT
// =====================================================================
__global__ void __launch_bounds__(256) combine_kernel()
{
    const int idx = blockIdx.x*256 + threadIdx.x;   // bh*NN + row
    const int bh = idx >> 12, row = idx & 4095;
    const int b = bh >> 2, h = bh & 3;

    float l = 0.f;
    float acc[16];
    #pragma unroll
    for (int d = 0; d < 16; d++) acc[d] = 0.f;

    #pragma unroll
    for (int z = 0; z < SPLIT; z++) {
        l += g_pl[z][idx];
        const float4* po = (const float4*)(g_po[z] + (size_t)idx*16);
        #pragma unroll
        for (int i = 0; i < 4; i++) {
            float4 v = po[i];
            acc[i*4+0] += v.x; acc[i*4+1] += v.y;
            acc[i*4+2] += v.z; acc[i*4+3] += v.w;
        }
    }
    const float inv = g_dyn[b*NN + row] / l;
    #pragma unroll
    for (int d = 0; d < 16; d++)
        g_ctxT[((size_t)(b*RED + h*HD + d))*NN + row] = acc[d] * inv;
}

// =====================================================================
// Kernel 3: out projection + residual + sigmoid
// =====================================================================
__global__ void __launch_bounds__(256) proj_kernel(
    const float* __restrict__ x,
    const float* __restrict__ ow,
    const float* __restrict__ gamma,
    float* __restrict__ out)
{
    __shared__ float cs[RED*33];
    const int tid  = threadIdx.x;
    const int tile = blockIdx.x;
    const int b    = tile >> 7;
    const int n0   = (tile & 127) << 5;

    for (int idx = tid; idx < RED*32; idx += 256) {
        int r = idx >> 5, p = idx & 31;
        cs[r*33 + p] = g_ctxT[((size_t)(b*RED + r))*NN + n0 + p];
    }
    __syncthreads();

    const int w = tid >> 5, lane = tid & 31;
    const float gm = gamma[0];

    for (int k = 0; k < 32; k++) {
        int c = w*32 + k;
        const float4* wr = (const float4*)(ow + c*RED);
        float acc = 0.f;
        #pragma unroll
        for (int r4 = 0; r4 < 16; r4++) {
            float4 wv = wr[r4];
            acc = fmaf(cs[(r4*4+0)*33 + lane], wv.x, acc);
            acc = fmaf(cs[(r4*4+1)*33 + lane], wv.y, acc);
            acc = fmaf(cs[(r4*4+2)*33 + lane], wv.z, acc);
            acc = fmaf(cs[(r4*4+3)*33 + lane], wv.w, acc);
        }
        size_t gi = ((size_t)b*CC + c)*NN + n0 + lane;
        float z = fmaf(gm, acc, x[gi]);
        float e = ex2f(-z * LOG2E);
        out[gi] = 1.f / (1.f + e);
    }
}

// =====================================================================
extern "C" void kernel_launch(void* const* d_in, const int* in_sizes, int n_in,
                              void* d_out, int out_size)
{
    const float* x     = (const float*)d_in[0];
    const float* nw    = (const float*)d_in[1];
    const float* nb    = (const float*)d_in[2];
    const float* qw    = (const float*)d_in[3];
    const float* ow    = (const float*)d_in[4];
    const float* c1w   = (const float*)d_in[5];
    const float* c1b   = (const float*)d_in[6];
    const float* c2w   = (const float*)d_in[7];
    const float* c2b   = (const float*)d_in[8];
    const float* gamma = (const float*)d_in[9];
    float* out = (float*)d_out;

    ln_dyn_kernel<<<256, 256>>>(x, nw, nb, c1w, c1b, c2w, c2b);
    qkv_kernel<<<128, 256>>>(qw);
    kmax_kernel<<<8, 256>>>();
    attn_kernel<<<dim3(16, 8, SPLIT), 128>>>();
    combine_kernel<<<128, 256>>>();
    proj_kernel<<<256, 256>>>(x, ow, gamma, out);
}

// round 11
// speedup vs baseline: 2.3318x; 1.0277x over previous
#include <cuda_runtime.h>

#define BB 2
#define CC 256
#define NN 4096
#define RED 64
#define NH 4
#define HD 16
#define BH (BB*NH)
#define SPLIT 8
#define SCALE 0.25f
#define LOG2E 1.44269504f

// ---------------- scratch (device globals, no allocation) ----------------
__device__ float g_xn[(size_t)BB*NN*CC];         // normalized x, [b*N+n][c]
__device__ float g_q[(size_t)BH*NN*HD];          // [bh][n][d], pre-scaled by SCALE*log2e
__device__ float g_k[(size_t)BH*NN*HD];
__device__ float g_v[(size_t)BH*NN*HD];
__device__ float g_dyn[(size_t)BB*NN];           // per-pixel scalar
__device__ float g_ctxT[(size_t)BB*RED*NN];      // [b][r][n]
__device__ float g_po[SPLIT][(size_t)BH*NN*HD];  // partial ctx per split
__device__ float g_pl[SPLIT][(size_t)BH*NN];     // partial l per split
__device__ unsigned int g_kmax2[BH];             // max |k|^2 per bh (float bits)

__device__ __forceinline__ float ex2f(float x) {
    float r; asm("ex2.approx.ftz.f32 %0, %1;" : "=f"(r) : "f"(x)); return r;
}
__device__ __forceinline__ unsigned long long pack2(float lo, float hi) {
    unsigned long long r; asm("mov.b64 %0, {%1, %2};" : "=l"(r) : "f"(lo), "f"(hi)); return r;
}
__device__ __forceinline__ float2 unpack2(unsigned long long v) {
    float2 r; asm("mov.b64 {%0, %1}, %2;" : "=f"(r.x), "=f"(r.y) : "l"(v)); return r;
}
#define FMA2(acc, a, b) asm("fma.rn.f32x2 %0, %1, %2, %0;" : "+l"(acc) : "l"(a), "l"(b))
__device__ __forceinline__ unsigned long long fma2i(
    unsigned long long a, unsigned long long b, unsigned long long c) {
    unsigned long long d; asm("fma.rn.f32x2 %0, %1, %2, %3;" : "=l"(d) : "l"(a), "l"(b), "l"(c));
    return d;
}
__device__ __forceinline__ unsigned long long mul2i(
    unsigned long long a, unsigned long long b) {
    unsigned long long d; asm("mul.rn.f32x2 %0, %1, %2;" : "=l"(d) : "l"(a), "l"(b));
    return d;
}

// =====================================================================
// Kernel 1a: LayerNorm stats + dynamic-weight branch + write x_hat
// (also resets g_kmax2 for this launch — stream-ordered before kmax)
// =====================================================================
__global__ void __launch_bounds__(256) ln_dyn_kernel(
    const float* __restrict__ x,
    const float* __restrict__ nw, const float* __restrict__ nb,
    const float* __restrict__ c1w, const float* __restrict__ c1b,
    const float* __restrict__ c2w, const float* __restrict__ c2b)
{
    __shared__ float xs[CC*33];
    __shared__ float mus[32], rss[32];
    __shared__ float dynp[8][32];

    const int tid  = threadIdx.x;
    const int tile = blockIdx.x;
    const int b    = tile >> 7;
    const int n0   = (tile & 127) << 5;

    if (tile == 0 && tid < BH) g_kmax2[tid] = 0u;

    const float* xb = x + (size_t)b*CC*NN;
    for (int idx = tid; idx < CC*32; idx += 256) {
        int c = idx >> 5, p = idx & 31;
        xs[c*33 + p] = xb[(size_t)c*NN + n0 + p];
    }
    __syncthreads();

    const int w = tid >> 5, lane = tid & 31;

    for (int qi = 0; qi < 4; qi++) {
        int p = w*4 + qi;
        float s1 = 0.f, s2 = 0.f;
        #pragma unroll
        for (int k = 0; k < 8; k++) {
            float v = xs[(lane + 32*k)*33 + p];
            s1 += v; s2 = fmaf(v, v, s2);
        }
        #pragma unroll
        for (int off = 16; off > 0; off >>= 1) {
            s1 += __shfl_down_sync(0xffffffffu, s1, off);
            s2 += __shfl_down_sync(0xffffffffu, s2, off);
        }
        if (lane == 0) {
            float mu  = s1 * (1.f/256.f);
            float var = s2 * (1.f/256.f) - mu*mu;
            mus[p] = mu;
            rss[p] = rsqrtf(var + 1e-5f);
        }
    }
    __syncthreads();

    {
        const int o0 = w*16;
        float acc[16];
        #pragma unroll
        for (int i = 0; i < 16; i++) acc[i] = c1b[o0+i];
        const float4* w14 = (const float4*)c1w;
        for (int c4 = 0; c4 < 64; c4++) {
            float x0 = xs[(c4*4+0)*33 + lane];
            float x1 = xs[(c4*4+1)*33 + lane];
            float x2 = xs[(c4*4+2)*33 + lane];
            float x3 = xs[(c4*4+3)*33 + lane];
            #pragma unroll
            for (int i = 0; i < 16; i++) {
                float4 wv = w14[(o0+i)*64 + c4];
                acc[i] = fmaf(wv.x, x0, acc[i]);
                acc[i] = fmaf(wv.y, x1, acc[i]);
                acc[i] = fmaf(wv.z, x2, acc[i]);
                acc[i] = fmaf(wv.w, x3, acc[i]);
            }
        }
        float part = 0.f;
        #pragma unroll
        for (int i = 0; i < 16; i++)
            part = fmaf(fmaxf(acc[i], 0.f), c2w[o0+i], part);
        dynp[w][lane] = part;
    }
    __syncthreads();
    if (tid < 32) {
        float d = c2b[0];
        #pragma unroll
        for (int g = 0; g < 8; g++) d += dynp[g][tid];
        g_dyn[b*NN + n0 + tid] = d;
    }

    for (int idx = tid; idx < 32*CC; idx += 256) {
        int p = idx >> 8, c = idx & 255;
        float v = (xs[c*33 + p] - mus[p]) * rss[p] * nw[c] + nb[c];
        g_xn[((size_t)(b*NN + n0 + p))*CC + c] = v;
    }
}

// =====================================================================
// Kernel 1b: QKV projection as smem-tiled GEMM (f32x2 accumulate)
// =====================================================================
__global__ void __launch_bounds__(256) qkv_kernel(const float* __restrict__ qw)
{
    __shared__ float xs[64*33];      // [pixel][k], pad 33
    __shared__ float ws[32*194];     // [k][out], pad 194 (8B-aligned rows)

    const int tid = threadIdx.x;
    const int px0 = blockIdx.x*64;
    const int opg = tid & 15;
    const int pxg = tid >> 4;
    const int o0  = opg*12;
    const int p0  = pxg*4;

    unsigned long long acc[6][4];
    #pragma unroll
    for (int i = 0; i < 6; i++)
        #pragma unroll
        for (int j = 0; j < 4; j++) acc[i][j] = 0ull;

    for (int it = 0; it < 8; it++) {
        const int k0 = it*32;
        __syncthreads();
        for (int i = tid; i < 64*32; i += 256) {
            int p = i >> 5, c = i & 31;
            xs[p*33 + c] = g_xn[(size_t)(px0+p)*256 + k0 + c];
        }
        for (int i = tid; i < 192*32; i += 256) {
            int o = i >> 5, c = i & 31;
            ws[c*194 + o] = qw[(size_t)o*256 + k0 + c];
        }
        __syncthreads();

        #pragma unroll 4
        for (int kk = 0; kk < 32; kk++) {
            unsigned long long xv[4];
            #pragma unroll
            for (int j = 0; j < 4; j++) {
                float v = xs[(p0+j)*33 + kk];
                xv[j] = pack2(v, v);
            }
            #pragma unroll
            for (int i = 0; i < 6; i++) {
                unsigned long long wv =
                    *(const unsigned long long*)&ws[kk*194 + o0 + 2*i];
                FMA2(acc[i][0], wv, xv[0]);
                FMA2(acc[i][1], wv, xv[1]);
                FMA2(acc[i][2], wv, xv[2]);
                FMA2(acc[i][3], wv, xv[3]);
            }
        }
    }

    const unsigned long long qs2 = pack2(SCALE*LOG2E, SCALE*LOG2E);
    #pragma unroll
    for (int i = 0; i < 6; i++) {
        const int o = o0 + 2*i;
        const int part = o >> 6;
        const int r = o & 63;
        const int h = r >> 4, d = r & 15;
        #pragma unroll
        for (int j = 0; j < 4; j++) {
            const int px = px0 + p0 + j;
            const int b = px >> 12, n = px & 4095;
            size_t dst = ((size_t)(b*NH + h)*NN + n)*HD + d;
            unsigned long long val = acc[i][j];
            if      (part == 0) *(unsigned long long*)(g_q + dst) = mul2i(val, qs2);
            else if (part == 1) *(unsigned long long*)(g_k + dst) = val;
            else                *(unsigned long long*)(g_v + dst) = val;
        }
    }
}

// =====================================================================
// Kernel 1c: per-bh max |k|^2 via atomicMax on float bits (>=0 ordered)
// grid (8 bh, 8 row-chunks), 256 threads
// =====================================================================
__global__ void __launch_bounds__(256) kmax_kernel()
{
    __shared__ float red[256];
    const int bh = blockIdx.x, tid = threadIdx.x;
    const int r0 = blockIdx.y * 512;
    const float4* kg = ((const float4*)g_k) + (size_t)bh*NN*4;
    float mx = 0.f;
    for (int r = r0 + tid; r < r0 + 512; r += 256) {
        float4 a = kg[r*4+0], b = kg[r*4+1], c = kg[r*4+2], d = kg[r*4+3];
        float s = a.x*a.x;
        s = fmaf(a.y,a.y,s); s = fmaf(a.z,a.z,s); s = fmaf(a.w,a.w,s);
        s = fmaf(b.x,b.x,s); s = fmaf(b.y,b.y,s); s = fmaf(b.z,b.z,s); s = fmaf(b.w,b.w,s);
        s = fmaf(c.x,c.x,s); s = fmaf(c.y,c.y,s); s = fmaf(c.z,c.z,s); s = fmaf(c.w,c.w,s);
        s = fmaf(d.x,d.x,s); s = fmaf(d.y,d.y,s); s = fmaf(d.z,d.z,s); s = fmaf(d.w,d.w,s);
        mx = fmaxf(mx, s);
    }
    red[tid] = mx; __syncthreads();
    for (int off = 128; off > 0; off >>= 1) {
        if (tid < off) red[tid] = fmaxf(red[tid], red[tid+off]);
        __syncthreads();
    }
    if (tid == 0) atomicMax(&g_kmax2[bh], __float_as_uint(red[0]));
}

// =====================================================================
// Kernel 2: flash attention, f32x2, fixed per-row softmax offset,
// split-KV x8, TWO rows/thread, 2-column chunks (reg-lean, 5 blocks/SM).
// grid (16 qtiles, 8 bh, 8 splits), 128 threads.
// =====================================================================
__global__ void __launch_bounds__(128, 5) attn_kernel()
{
    __shared__ ulonglong2 Ks[512];   // 128 rows x 4 x 16B
    __shared__ ulonglong2 Vs[512];

    const int tid = threadIdx.x;
    const int bh  = blockIdx.y;
    const int z   = blockIdx.z;
    const int rowA = blockIdx.x*256 + tid;     // rowB = rowA + 128
    const float km = sqrtf(__uint_as_float(g_kmax2[bh]));

    const float4* qfA = ((const float4*)g_q) + ((size_t)bh*NN + rowA)*4;
    const float4 a0 = qfA[0], a1 = qfA[1], a2 = qfA[2], a3 = qfA[3];
    const float4 b0 = qfA[512], b1 = qfA[513], b2 = qfA[514], b3 = qfA[515];

    float nA = a0.x*a0.x;
    nA = fmaf(a0.y,a0.y,nA); nA = fmaf(a0.z,a0.z,nA); nA = fmaf(a0.w,a0.w,nA);
    nA = fmaf(a1.x,a1.x,nA); nA = fmaf(a1.y,a1.y,nA); nA = fmaf(a1.z,a1.z,nA); nA = fmaf(a1.w,a1.w,nA);
    nA = fmaf(a2.x,a2.x,nA); nA = fmaf(a2.y,a2.y,nA); nA = fmaf(a2.z,a2.z,nA); nA = fmaf(a2.w,a2.w,nA);
    nA = fmaf(a3.x,a3.x,nA); nA = fmaf(a3.y,a3.y,nA); nA = fmaf(a3.z,a3.z,nA); nA = fmaf(a3.w,a3.w,nA);
    float nB = b0.x*b0.x;
    nB = fmaf(b0.y,b0.y,nB); nB = fmaf(b0.z,b0.z,nB); nB = fmaf(b0.w,b0.w,nB);
    nB = fmaf(b1.x,b1.x,nB); nB = fmaf(b1.y,b1.y,nB); nB = fmaf(b1.z,b1.z,nB); nB = fmaf(b1.w,b1.w,nB);
    nB = fmaf(b2.x,b2.x,nB); nB = fmaf(b2.y,b2.y,nB); nB = fmaf(b2.z,b2.z,nB); nB = fmaf(b2.w,b2.w,nB);
    nB = fmaf(b3.x,b3.x,nB); nB = fmaf(b3.y,b3.y,nB); nB = fmaf(b3.z,b3.z,nB); nB = fmaf(b3.w,b3.w,nB);
    const unsigned long long miA = pack2(-sqrtf(nA)*km, 0.f);
    const unsigned long long miB = pack2(-sqrtf(nB)*km, 0.f);

    const unsigned long long qA[8] = {
        pack2(a0.x,a0.y), pack2(a0.z,a0.w), pack2(a1.x,a1.y), pack2(a1.z,a1.w),
        pack2(a2.x,a2.y), pack2(a2.z,a2.w), pack2(a3.x,a3.y), pack2(a3.z,a3.w)};
    const unsigned long long qB[8] = {
        pack2(b0.x,b0.y), pack2(b0.z,b0.w), pack2(b1.x,b1.y), pack2(b1.z,b1.w),
        pack2(b2.x,b2.y), pack2(b2.z,b2.w), pack2(b3.x,b3.y), pack2(b3.z,b3.w)};

    const unsigned long long one2 = pack2(1.f, 1.f);
    unsigned long long oA[8], oB[8];
    #pragma unroll
    for (int d = 0; d < 8; d++) { oA[d] = 0ull; oB[d] = 0ull; }
    unsigned long long lAB = 0ull;   // (lA, lB) packed

    const ulonglong2* kg = ((const ulonglong2*)g_k) + (size_t)bh*NN*4;
    const ulonglong2* vg = ((const ulonglong2*)g_v) + (size_t)bh*NN*4;

    for (int kt = z*4; kt < z*4 + 4; kt++) {
        __syncthreads();
        #pragma unroll
        for (int i = 0; i < 4; i++) {
            Ks[tid + i*128] = kg[kt*512 + tid + i*128];
            Vs[tid + i*128] = vg[kt*512 + tid + i*128];
        }
        __syncthreads();

        #pragma unroll 1
        for (int c0 = 0; c0 < 128; c0 += 2) {
            float pA0, pB0, pA1, pB1;
            {
                const ulonglong2* kk = &Ks[c0*4];
                const ulonglong2 k00 = kk[0], k01 = kk[1], k02 = kk[2], k03 = kk[3];
                const ulonglong2 k10 = kk[4], k11 = kk[5], k12 = kk[6], k13 = kk[7];
                unsigned long long sa0 = fma2i(qA[0], k00.x, miA);
                unsigned long long sb0 = fma2i(qB[0], k00.x, miB);
                unsigned long long sa1 = fma2i(qA[0], k10.x, miA);
                unsigned long long sb1 = fma2i(qB[0], k10.x, miB);
                FMA2(sa0,qA[1],k00.y); FMA2(sb0,qB[1],k00.y); FMA2(sa1,qA[1],k10.y); FMA2(sb1,qB[1],k10.y);
                FMA2(sa0,qA[2],k01.x); FMA2(sb0,qB[2],k01.x); FMA2(sa1,qA[2],k11.x); FMA2(sb1,qB[2],k11.x);
                FMA2(sa0,qA[3],k01.y); FMA2(sb0,qB[3],k01.y); FMA2(sa1,qA[3],k11.y); FMA2(sb1,qB[3],k11.y);
                FMA2(sa0,qA[4],k02.x); FMA2(sb0,qB[4],k02.x); FMA2(sa1,qA[4],k12.x); FMA2(sb1,qB[4],k12.x);
                FMA2(sa0,qA[5],k02.y); FMA2(sb0,qB[5],k02.y); FMA2(sa1,qA[5],k12.y); FMA2(sb1,qB[5],k12.y);
                FMA2(sa0,qA[6],k03.x); FMA2(sb0,qB[6],k03.x); FMA2(sa1,qA[6],k13.x); FMA2(sb1,qB[6],k13.x);
                FMA2(sa0,qA[7],k03.y); FMA2(sb0,qB[7],k03.y); FMA2(sa1,qA[7],k13.y); FMA2(sb1,qB[7],k13.y);
                float2 va0 = unpack2(sa0), vb0 = unpack2(sb0);
                float2 va1 = unpack2(sa1), vb1 = unpack2(sb1);
                pA0 = ex2f(va0.x + va0.y); pB0 = ex2f(vb0.x + vb0.y);
                pA1 = ex2f(va1.x + va1.y); pB1 = ex2f(vb1.x + vb1.y);
            }
            lAB = fma2i(pack2(pA0, pB0), one2, lAB);
            lAB = fma2i(pack2(pA1, pB1), one2, lAB);
            {
                const unsigned long long ppA0 = pack2(pA0, pA0), ppB0 = pack2(pB0, pB0);
                const unsigned long long ppA1 = pack2(pA1, pA1), ppB1 = pack2(pB1, pB1);
                const ulonglong2* vv = &Vs[c0*4];
                const ulonglong2 v00 = vv[0], v01 = vv[1], v02 = vv[2], v03 = vv[3];
                const ulonglong2 v10 = vv[4], v11 = vv[5], v12 = vv[6], v13 = vv[7];
                FMA2(oA[0], ppA0, v00.x); FMA2(oB[0], ppB0, v00.x);
                FMA2(oA[1], ppA0, v00.y); FMA2(oB[1], ppB0, v00.y);
                FMA2(oA[2], ppA0, v01.x); FMA2(oB[2], ppB0, v01.x);
                FMA2(oA[3], ppA0, v01.y); FMA2(oB[3], ppB0, v01.y);
                FMA2(oA[4], ppA0, v02.x); FMA2(oB[4], ppB0, v02.x);
                FMA2(oA[5], ppA0, v02.y); FMA2(oB[5], ppB0, v02.y);
                FMA2(oA[6], ppA0, v03.x); FMA2(oB[6], ppB0, v03.x);
                FMA2(oA[7], ppA0, v03.y); FMA2(oB[7], ppB0, v03.y);
                FMA2(oA[0], ppA1, v10.x); FMA2(oB[0], ppB1, v10.x);
                FMA2(oA[1], ppA1, v10.y); FMA2(oB[1], ppB1, v10.y);
                FMA2(oA[2], ppA1, v11.x); FMA2(oB[2], ppB1, v11.x);
                FMA2(oA[3], ppA1, v11.y); FMA2(oB[3], ppB1, v11.y);
                FMA2(oA[4], ppA1, v12.x); FMA2(oB[4], ppB1, v12.x);
                FMA2(oA[5], ppA1, v12.y); FMA2(oB[5], ppB1, v12.y);
                FMA2(oA[6], ppA1, v13.x); FMA2(oB[6], ppB1, v13.x);
                FMA2(oA[7], ppA1, v13.y); FMA2(oB[7], ppB1, v13.y);
            }
        }
    }

    float* poA = g_po[z] + ((size_t)bh*NN + rowA)*16;
    #pragma unroll
    for (int i = 0; i < 4; i++) {
        ulonglong2 w; w.x = oA[2*i]; w.y = oA[2*i+1];
        *(ulonglong2*)(poA + i*4) = w;
    }
    float* poB = poA + 128*16;
    #pragma unroll
    for (int i = 0; i < 4; i++) {
        ulonglong2 w; w.x = oB[2*i]; w.y = oB[2*i+1];
        *(ulonglong2*)(poB + i*4) = w;
    }
    float2 lv = unpack2(lAB);
    g_pl[z][(size_t)bh*NN + rowA]       = lv.x;
    g_pl[z][(size_t)bh*NN + rowA + 128] = lv.y;
}

// =====================================================================
// Kernel 2b: combine split partials, normalize, apply dyn, write ctxT
// =====================================================================
__global__ void __launch_bounds__(256) combine_kernel()
{
    const int idx = blockIdx.x*256 + threadIdx.x;   // bh*NN + row
    const int bh = idx >> 12, row = idx & 4095;
    const int b = bh >> 2, h = bh & 3;

    float l = 0.f;
    float acc[16];
    #pragma unroll
    for (int d = 0; d < 16; d++) acc[d] = 0.f;

    #pragma unroll
    for (int z = 0; z < SPLIT; z++) {
        l += g_pl[z][idx];
        const float4* po = (const float4*)(g_po[z] + (size_t)idx*16);
        #pragma unroll
        for (int i = 0; i < 4; i++) {
            float4 v = po[i];
            acc[i*4+0] += v.x; acc[i*4+1] += v.y;
            acc[i*4+2] += v.z; acc[i*4+3] += v.w;
        }
    }
    const float inv = g_dyn[b*NN + row] / l;
    #pragma unroll
    for (int d = 0; d < 16; d++)
        g_ctxT[((size_t)(b*RED + h*HD + d))*NN + row] = acc[d] * inv;
}

// =====================================================================
// Kernel 3: out projection + residual + sigmoid. grid (256 tiles, 2 halves)
// =====================================================================
__global__ void __launch_bounds__(256) proj_kernel(
    const float* __restrict__ x,
    const float* __restrict__ ow,
    const float* __restrict__ gamma,
    float* __restrict__ out)
{
    __shared__ float cs[RED*33];
    const int tid  = threadIdx.x;
    const int tile = blockIdx.x;
    const int half = blockIdx.y;
    const int b    = tile >> 7;
    const int n0   = (tile & 127) << 5;

    for (int idx = tid; idx < RED*32; idx += 256) {
        int r = idx >> 5, p = idx & 31;
        cs[r*33 + p] = g_ctxT[((size_t)(b*RED + r))*NN + n0 + p];
    }
    __syncthreads();

    const int w = tid >> 5, lane = tid & 31;
    const float gm = gamma[0];

    for (int k = 0; k < 16; k++) {
        int c = w*32 + half*16 + k;
        const float4* wr = (const float4*)(ow + c*RED);
        float acc = 0.f;
        #pragma unroll
        for (int r4 = 0; r4 < 16; r4++) {
            float4 wv = wr[r4];
            acc = fmaf(cs[(r4*4+0)*33 + lane], wv.x, acc);
            acc = fmaf(cs[(r4*4+1)*33 + lane], wv.y, acc);
            acc = fmaf(cs[(r4*4+2)*33 + lane], wv.z, acc);
            acc = fmaf(cs[(r4*4+3)*33 + lane], wv.w, acc);
        }
        size_t gi = ((size_t)b*CC + c)*NN + n0 + lane;
        float z = fmaf(gm, acc, x[gi]);
        float e = ex2f(-z * LOG2E);
        out[gi] = 1.f / (1.f + e);
    }
}

// =====================================================================
extern "C" void kernel_launch(void* const* d_in, const int* in_sizes, int n_in,
                              void* d_out, int out_size)
{
    const float* x     = (const float*)d_in[0];
    const float* nw    = (const float*)d_in[1];
    const float* nb    = (const float*)d_in[2];
    const float* qw    = (const float*)d_in[3];
    const float* ow    = (const float*)d_in[4];
    const float* c1w   = (const float*)d_in[5];
    const float* c1b   = (const float*)d_in[6];
    const float* c2w   = (const float*)d_in[7];
    const float* c2b   = (const float*)d_in[8];
    const float* gamma = (const float*)d_in[9];
    float* out = (float*)d_out;

    ln_dyn_kernel<<<256, 256>>>(x, nw, nb, c1w, c1b, c2w, c2b);
    qkv_kernel<<<128, 256>>>(qw);
    kmax_kernel<<<dim3(8, 8), 256>>>();
    attn_kernel<<<dim3(16, 8, SPLIT), 128>>>();
    combine_kernel<<<128, 256>>>();
    proj_kernel<<<dim3(256, 2), 256>>>(x, ow, gamma, out);
}